// round 3
// baseline (speedup 1.0000x reference)
#include <cuda_runtime.h>
#include <math.h>

#define NMAX 100000
#define EMAX 1600000

typedef unsigned long long u64;

// ---------------- scratch (no allocations allowed) ----------------
__device__ __align__(16) float g_hA[NMAX * 8];
__device__ __align__(16) float g_hB[NMAX * 8];
__device__ __align__(16) float g_p1[NMAX * 64];
__device__ __align__(16) float g_p2[NMAX * 64];
__device__ float g_w[EMAX];
__device__ float g_he[EMAX];
__device__ float g_agg[NMAX];
__device__ float g_s[NMAX];
__device__ unsigned int g_m[NMAX];

// ---------------- packed f32x2 helpers ----------------
__device__ __forceinline__ u64 pk2(float lo, float hi) {
    u64 r;
    asm("mov.b64 %0, {%1,%2};" : "=l"(r) : "f"(lo), "f"(hi));
    return r;
}
__device__ __forceinline__ void upk2(u64 v, float& lo, float& hi) {
    asm("mov.b64 {%0,%1}, %2;" : "=f"(lo), "=f"(hi) : "l"(v));
}
__device__ __forceinline__ u64 dup2(float v) { return pk2(v, v); }
__device__ __forceinline__ u64 ffma2(u64 a, u64 b, u64 c) {
    u64 d;
    asm("fma.rn.f32x2 %0, %1, %2, %3;" : "=l"(d) : "l"(a), "l"(b), "l"(c));
    return d;
}
__device__ __forceinline__ u64 add2(u64 a, u64 b) {
    u64 d;
    asm("add.rn.f32x2 %0, %1, %2;" : "=l"(d) : "l"(a), "l"(b));
    return d;
}
__device__ __forceinline__ u64 relu2(u64 v) {
    float a, b;
    upk2(v, a, b);
    return pk2(fmaxf(a, 0.f), fmaxf(b, 0.f));
}

// ---------------- ordered-float helpers for atomicMax ----------------
__device__ __forceinline__ unsigned f2o(float f) {
    unsigned u = __float_as_uint(f);
    return (u & 0x80000000u) ? ~u : (u | 0x80000000u);
}
__device__ __forceinline__ float o2f(unsigned o) {
    return (o & 0x80000000u) ? __uint_as_float(o ^ 0x80000000u)
                             : __uint_as_float(~o);
}

// ---------------- softmax helper kernels ----------------
__global__ void k_segmax(const float* __restrict__ dist,
                         const int* __restrict__ dst,
                         unsigned* __restrict__ m, int E) {
    int e = blockIdx.x * blockDim.x + threadIdx.x;
    if (e >= E) return;
    atomicMax(&m[dst[e]], f2o(dist[e]));
}

__global__ void k_segexp(const float* __restrict__ dist,
                         const int* __restrict__ dst,
                         const unsigned* __restrict__ m,
                         float* __restrict__ w, float* __restrict__ s, int E) {
    int e = blockIdx.x * blockDim.x + threadIdx.x;
    if (e >= E) return;
    int d = dst[e];
    float ev = expf(dist[e] - o2f(m[d]));
    w[e] = ev;  // unnormalized; node-side divide later
    atomicAdd(&s[d], ev);
}

// h_out[dst] += w[e] * h[src]   (8 lanes, unnormalized w)
__global__ void k_agg8(const float* __restrict__ w, const float* __restrict__ h,
                       const int* __restrict__ src, const int* __restrict__ dst,
                       float* __restrict__ ho, int E) {
    int e = blockIdx.x * blockDim.x + threadIdx.x;
    if (e >= E) return;
    float we = w[e];
    int sn = src[e], dn = dst[e];
    const float4* hp = (const float4*)(h + (size_t)sn * 8);
    float4 a = hp[0], b = hp[1];
    float* o = ho + (size_t)dn * 8;
    atomicAdd(o + 0, we * a.x);
    atomicAdd(o + 1, we * a.y);
    atomicAdd(o + 2, we * a.z);
    atomicAdd(o + 3, we * a.w);
    atomicAdd(o + 4, we * b.x);
    atomicAdd(o + 5, we * b.y);
    atomicAdd(o + 6, we * b.z);
    atomicAdd(o + 7, we * b.w);
}

// h[n][0..7] *= (s[n] > 0 ? 1/s[n] : 0)
__global__ void k_scale8(float* __restrict__ h, const float* __restrict__ s,
                         int N) {
    int i = blockIdx.x * blockDim.x + threadIdx.x;
    if (i >= N * 8) return;
    float sv = s[i >> 3];
    float inv = (sv > 0.f) ? (1.f / sv) : 0.f;
    h[i] *= inv;
}

// ---------------- per-node projections for edge MLP layer 1 ----------------
// p1[n][k] = sum_i h[n][i] * w1[(1+i)*64+k]
// p2[n][k] = sum_i h[n][i] * w1[(9+i)*64+k] + b1[k]
__global__ __launch_bounds__(128) void k_proj(
    const float* __restrict__ h, const float* __restrict__ w1,
    const float* __restrict__ b1, float* __restrict__ p1,
    float* __restrict__ p2, int N) {
    __shared__ __align__(16) float s_ws[8 * 64];
    __shared__ __align__(16) float s_wd[8 * 64];
    __shared__ __align__(16) float s_b1[64];
    for (int i = threadIdx.x; i < 512; i += 128) {
        s_ws[i] = w1[64 + i];
        s_wd[i] = w1[64 * 9 + i];
    }
    if (threadIdx.x < 64) s_b1[threadIdx.x] = b1[threadIdx.x];
    __syncthreads();

    int n = blockIdx.x * 128 + threadIdx.x;
    if (n >= N) return;

    float hv[8];
    {
        const float4* p = (const float4*)(h + (size_t)n * 8);
        float4 a = p[0], b = p[1];
        hv[0] = a.x; hv[1] = a.y; hv[2] = a.z; hv[3] = a.w;
        hv[4] = b.x; hv[5] = b.y; hv[6] = b.z; hv[7] = b.w;
    }

    const u64* wsp = (const u64*)s_ws;
    const u64* wdp = (const u64*)s_wd;
    const u64* b1p = (const u64*)s_b1;
    u64 a1[32], a2[32];
#pragma unroll
    for (int kp = 0; kp < 32; kp++) {
        a1[kp] = 0ull;
        a2[kp] = b1p[kp];
    }
#pragma unroll
    for (int i = 0; i < 8; i++) {
        u64 x2 = dup2(hv[i]);
#pragma unroll
        for (int kp = 0; kp < 32; kp++) {
            a1[kp] = ffma2(x2, wsp[i * 32 + kp], a1[kp]);
            a2[kp] = ffma2(x2, wdp[i * 32 + kp], a2[kp]);
        }
    }
    ulonglong2* o1 = (ulonglong2*)(p1 + (size_t)n * 64);
    ulonglong2* o2 = (ulonglong2*)(p2 + (size_t)n * 64);
#pragma unroll
    for (int q = 0; q < 16; q++) {
        ulonglong2 v1, v2;
        v1.x = a1[2 * q]; v1.y = a1[2 * q + 1];
        v2.x = a2[2 * q]; v2.y = a2[2 * q + 1];
        o1[q] = v1;
        o2[q] = v2;
    }
}

// ---------------- generic per-node MLP: D0 -> 64 -> 64 -> DOUT (relu x3) ----
// Input x[i] = i < SPLIT ? xa[n*SPLIT + i] : xb[n*8 + (i-SPLIT)]
template <int D0, int SPLIT, int DOUT>
__global__ __launch_bounds__(128) void k_node_mlp(
    const float* __restrict__ xa, const float* __restrict__ xb,
    const float* __restrict__ w1, const float* __restrict__ b1,
    const float* __restrict__ w2, const float* __restrict__ b2,
    const float* __restrict__ w3, const float* __restrict__ b3,
    float* __restrict__ out, int N) {
    __shared__ __align__(16) float s_w1[D0 * 64];
    __shared__ __align__(16) float s_w2t[64 * 64];
    __shared__ __align__(16) float s_w3[64 * DOUT];
    __shared__ __align__(16) float s_b1[64];
    __shared__ __align__(16) float s_b3p[(DOUT + 1) & ~1];
    __shared__ float s_b2[64];

    for (int i = threadIdx.x; i < D0 * 64; i += 128) s_w1[i] = w1[i];
    for (int i = threadIdx.x; i < 64 * 64; i += 128) {
        int k = i >> 6, j = i & 63;
        s_w2t[i] = w2[j * 64 + k];  // transpose: s_w2t[k][j]
    }
    for (int i = threadIdx.x; i < 64 * DOUT; i += 128) s_w3[i] = w3[i];
    if (threadIdx.x < 64) {
        s_b1[threadIdx.x] = b1[threadIdx.x];
        s_b2[threadIdx.x] = b2[threadIdx.x];
    }
    if (threadIdx.x < DOUT) s_b3p[threadIdx.x] = b3[threadIdx.x];
    __syncthreads();

    int n = blockIdx.x * 128 + threadIdx.x;
    if (n >= N) return;

    float xv[D0];
#pragma unroll
    for (int i = 0; i < SPLIT; i++) xv[i] = xa[(size_t)n * SPLIT + i];
    if constexpr (SPLIT < D0) {
#pragma unroll
        for (int i = 0; i < D0 - SPLIT; i++)
            xv[SPLIT + i] = xb[(size_t)n * 8 + i];
    }

    const ulonglong2* w1p = (const ulonglong2*)s_w1;
    const u64* b1p = (const u64*)s_b1;
    u64 h1[32];
#pragma unroll
    for (int kp = 0; kp < 32; kp++) h1[kp] = b1p[kp];
#pragma unroll 4
    for (int i = 0; i < D0; i++) {
        u64 x2 = dup2(xv[i]);
#pragma unroll
        for (int q = 0; q < 16; q++) {
            ulonglong2 wv = w1p[i * 16 + q];
            h1[2 * q] = ffma2(x2, wv.x, h1[2 * q]);
            h1[2 * q + 1] = ffma2(x2, wv.y, h1[2 * q + 1]);
        }
    }
#pragma unroll
    for (int kp = 0; kp < 32; kp++) h1[kp] = relu2(h1[kp]);

    const ulonglong2* w2p = (const ulonglong2*)s_w2t;

    if constexpr (DOUT == 1) {
        float o = s_b3p[0];
#pragma unroll 4
        for (int k = 0; k < 64; k++) {
            u64 acc = 0ull;
#pragma unroll
            for (int q = 0; q < 16; q++) {
                ulonglong2 wv = w2p[k * 16 + q];
                acc = ffma2(h1[2 * q], wv.x, acc);
                acc = ffma2(h1[2 * q + 1], wv.y, acc);
            }
            float al, ah;
            upk2(acc, al, ah);
            float h2 = fmaxf(al + ah + s_b2[k], 0.f);
            o = fmaf(h2, s_w3[k], o);
        }
        out[n] = fmaxf(o, 0.f);
    } else {
        const u64* w3p = (const u64*)s_w3;
        const u64* b3pp = (const u64*)s_b3p;
        u64 op[DOUT / 2];
#pragma unroll
        for (int dp = 0; dp < DOUT / 2; dp++) op[dp] = b3pp[dp];
#pragma unroll 4
        for (int k = 0; k < 64; k++) {
            u64 acc = 0ull;
#pragma unroll
            for (int q = 0; q < 16; q++) {
                ulonglong2 wv = w2p[k * 16 + q];
                acc = ffma2(h1[2 * q], wv.x, acc);
                acc = ffma2(h1[2 * q + 1], wv.y, acc);
            }
            float al, ah;
            upk2(acc, al, ah);
            u64 h2d = dup2(fmaxf(al + ah + s_b2[k], 0.f));
#pragma unroll
            for (int dp = 0; dp < DOUT / 2; dp++)
                op[dp] = ffma2(h2d, w3p[k * (DOUT / 2) + dp], op[dp]);
        }
#pragma unroll
        for (int dp = 0; dp < DOUT / 2; dp++) {
            float a, b;
            upk2(op[dp], a, b);
            out[(size_t)n * DOUT + 2 * dp] = fmaxf(a, 0.f);
            out[(size_t)n * DOUT + 2 * dp + 1] = fmaxf(b, 0.f);
        }
    }
}

// ---------------- edge MLP using precomputed projections --------------------
// h1 = relu(he*w_he + p1[src] + p2[dst]);  out = relu(w3 . relu(W2 h1) + b3)
// 2 edges per thread; writes he_out[e], atomicAdds into agg[dst].
__global__ __launch_bounds__(128) void k_edge_mlp(
    const float* __restrict__ he_in, const float* __restrict__ p1,
    const float* __restrict__ p2, const int* __restrict__ src,
    const int* __restrict__ dst, const float* __restrict__ w1,
    const float* __restrict__ w2, const float* __restrict__ b2,
    const float* __restrict__ w3, const float* __restrict__ b3,
    float* __restrict__ he_out, float* __restrict__ agg, int E) {
    __shared__ __align__(16) float s_w2t[64 * 64];
    __shared__ __align__(16) float s_whe[64];
    __shared__ float s_b2[64], s_w3[64], s_b3;

    for (int i = threadIdx.x; i < 64 * 64; i += 128) {
        int k = i >> 6, j = i & 63;
        s_w2t[i] = w2[j * 64 + k];  // transpose
    }
    if (threadIdx.x < 64) {
        s_whe[threadIdx.x] = w1[threadIdx.x];  // row 0 of W1
        s_b2[threadIdx.x] = b2[threadIdx.x];
        s_w3[threadIdx.x] = w3[threadIdx.x];
    }
    if (threadIdx.x == 0) s_b3 = b3[0];
    __syncthreads();

    int t = blockIdx.x * 128 + threadIdx.x;
    int e0 = 2 * t;
    if (e0 >= E) return;
    bool has1 = (e0 + 1 < E);

    int s0, d0, s1, d1;
    float he0, he1;
    if (has1) {
        int2 sv = ((const int2*)src)[t];
        int2 dv = ((const int2*)dst)[t];
        float2 hv = ((const float2*)he_in)[t];
        s0 = sv.x; s1 = sv.y;
        d0 = dv.x; d1 = dv.y;
        he0 = hv.x; he1 = hv.y;
    } else {
        s0 = s1 = src[e0];
        d0 = d1 = dst[e0];
        he0 = he1 = he_in[e0];
    }

    const ulonglong2* P1s0 = (const ulonglong2*)(p1 + (size_t)s0 * 64);
    const ulonglong2* P2d0 = (const ulonglong2*)(p2 + (size_t)d0 * 64);
    const ulonglong2* P1s1 = (const ulonglong2*)(p1 + (size_t)s1 * 64);
    const ulonglong2* P2d1 = (const ulonglong2*)(p2 + (size_t)d1 * 64);
    const ulonglong2* whe = (const ulonglong2*)s_whe;

    u64 he0d = dup2(he0), he1d = dup2(he1);
    u64 h0[32], h1v[32];
#pragma unroll
    for (int q = 0; q < 16; q++) {
        ulonglong2 wv = whe[q];
        ulonglong2 a0 = P1s0[q], b0 = P2d0[q];
        ulonglong2 a1 = P1s1[q], b1v = P2d1[q];
        h0[2 * q] = relu2(ffma2(he0d, wv.x, add2(a0.x, b0.x)));
        h0[2 * q + 1] = relu2(ffma2(he0d, wv.y, add2(a0.y, b0.y)));
        h1v[2 * q] = relu2(ffma2(he1d, wv.x, add2(a1.x, b1v.x)));
        h1v[2 * q + 1] = relu2(ffma2(he1d, wv.y, add2(a1.y, b1v.y)));
    }

    const ulonglong2* w2p = (const ulonglong2*)s_w2t;
    float out0 = s_b3, out1 = s_b3;
#pragma unroll 2
    for (int k = 0; k < 64; k++) {
        u64 acc0 = 0ull, acc1 = 0ull;
#pragma unroll
        for (int q = 0; q < 16; q++) {
            ulonglong2 wv = w2p[k * 16 + q];
            acc0 = ffma2(h0[2 * q], wv.x, acc0);
            acc1 = ffma2(h1v[2 * q], wv.x, acc1);
            acc0 = ffma2(h0[2 * q + 1], wv.y, acc0);
            acc1 = ffma2(h1v[2 * q + 1], wv.y, acc1);
        }
        float al, ah, bl, bh;
        upk2(acc0, al, ah);
        upk2(acc1, bl, bh);
        float w3k = s_w3[k], b2k = s_b2[k];
        out0 = fmaf(fmaxf(al + ah + b2k, 0.f), w3k, out0);
        out1 = fmaf(fmaxf(bl + bh + b2k, 0.f), w3k, out1);
    }

    out0 = fmaxf(out0, 0.f);
    he_out[e0] = out0;
    atomicAdd(&agg[d0], out0);
    if (has1) {
        out1 = fmaxf(out1, 0.f);
        he_out[e0 + 1] = out1;
        atomicAdd(&agg[d1], out1);
    }
}

// ---------------- launch ----------------
extern "C" void kernel_launch(void* const* d_in, const int* in_sizes, int n_in,
                              void* d_out, int out_size) {
    const float* node_feat = (const float*)d_in[0];
    const float* edge_feat = (const float*)d_in[1];
    const float* edge_dist = (const float*)d_in[2];
    const int* src = (const int*)d_in[3];
    const int* dst = (const int*)d_in[4];

    const float* w_enc1 = (const float*)d_in[5];
    const float* b_enc1 = (const float*)d_in[6];
    const float* w_enc2 = (const float*)d_in[7];
    const float* b_enc2 = (const float*)d_in[8];
    const float* w_enc3 = (const float*)d_in[9];
    const float* b_enc3 = (const float*)d_in[10];

    const float* w_dec1 = (const float*)d_in[11];
    const float* b_dec1 = (const float*)d_in[12];
    const float* w_dec2 = (const float*)d_in[13];
    const float* b_dec2 = (const float*)d_in[14];
    const float* w_dec3 = (const float*)d_in[15];
    const float* b_dec3 = (const float*)d_in[16];

    const float* w_nod1 = (const float*)d_in[17];
    const float* b_nod1 = (const float*)d_in[18];
    const float* w_nod2 = (const float*)d_in[19];
    const float* b_nod2 = (const float*)d_in[20];
    const float* w_nod3 = (const float*)d_in[21];
    const float* b_nod3 = (const float*)d_in[22];

    const float* w_edg1 = (const float*)d_in[23];
    const float* b_edg1 = (const float*)d_in[24];
    const float* w_edg2 = (const float*)d_in[25];
    const float* b_edg2 = (const float*)d_in[26];
    const float* w_edg3 = (const float*)d_in[27];
    const float* b_edg3 = (const float*)d_in[28];

    int N = in_sizes[0] / 3;
    int E = in_sizes[1];

    float *hA, *hB, *wbuf, *hebuf, *aggbuf, *sbuf, *p1, *p2;
    unsigned* mbuf;
    cudaGetSymbolAddress((void**)&hA, g_hA);
    cudaGetSymbolAddress((void**)&hB, g_hB);
    cudaGetSymbolAddress((void**)&wbuf, g_w);
    cudaGetSymbolAddress((void**)&hebuf, g_he);
    cudaGetSymbolAddress((void**)&aggbuf, g_agg);
    cudaGetSymbolAddress((void**)&sbuf, g_s);
    cudaGetSymbolAddress((void**)&mbuf, g_m);
    cudaGetSymbolAddress((void**)&p1, g_p1);
    cudaGetSymbolAddress((void**)&p2, g_p2);

    int gN128 = (N + 127) / 128;
    int gN8 = (N * 8 + 255) / 256;
    int gE = (E + 255) / 256;
    int gE2 = (E + 255) / 256;  // edge MLP: 128 thr x 2 edges = 256 edges/blk

    // encoder: [N,3] -> hA [N,8]
    k_node_mlp<3, 3, 8><<<gN128, 128>>>(node_feat, nullptr, w_enc1, b_enc1,
                                        w_enc2, b_enc2, w_enc3, b_enc3, hA, N);

    // edge softmax (unnormalized weights in wbuf, sums in sbuf)
    cudaMemsetAsync(mbuf, 0, (size_t)N * 4);
    k_segmax<<<gE, 256>>>(edge_dist, dst, mbuf, E);
    cudaMemsetAsync(sbuf, 0, (size_t)N * 4);
    k_segexp<<<gE, 256>>>(edge_dist, dst, mbuf, wbuf, sbuf, E);

    // h = segsum(w * hA[src], dst) / s -> hB
    cudaMemsetAsync(hB, 0, (size_t)N * 8 * 4);
    k_agg8<<<gE, 256>>>(wbuf, hA, src, dst, hB, E);
    k_scale8<<<gN8, 256>>>(hB, sbuf, N);

    // iteration 1 (h = hB, he = edge_feat)
    k_proj<<<gN128, 128>>>(hB, w_edg1, b_edg1, p1, p2, N);
    cudaMemsetAsync(aggbuf, 0, (size_t)N * 4);
    k_edge_mlp<<<gE2, 128>>>(edge_feat, p1, p2, src, dst, w_edg1, w_edg2,
                             b_edg2, w_edg3, b_edg3, hebuf, aggbuf, E);
    k_node_mlp<9, 1, 8><<<gN128, 128>>>(aggbuf, hB, w_nod1, b_nod1, w_nod2,
                                        b_nod2, w_nod3, b_nod3, hA, N);

    // iteration 2 (h = hA, he = hebuf)
    k_proj<<<gN128, 128>>>(hA, w_edg1, b_edg1, p1, p2, N);
    cudaMemsetAsync(aggbuf, 0, (size_t)N * 4);
    k_edge_mlp<<<gE2, 128>>>(hebuf, p1, p2, src, dst, w_edg1, w_edg2, b_edg2,
                             w_edg3, b_edg3, hebuf, aggbuf, E);
    k_node_mlp<9, 1, 8><<<gN128, 128>>>(aggbuf, hA, w_nod1, b_nod1, w_nod2,
                                        b_nod2, w_nod3, b_nod3, hB, N);

    // final softmax aggregation: hA = segsum(w * hB[src], dst) / s
    cudaMemsetAsync(hA, 0, (size_t)N * 8 * 4);
    k_agg8<<<gE, 256>>>(wbuf, hB, src, dst, hA, E);
    k_scale8<<<gN8, 256>>>(hA, sbuf, N);

    // decoder: hA [N,8] -> out [N,1]
    k_node_mlp<8, 8, 1><<<gN128, 128>>>(hA, nullptr, w_dec1, b_dec1, w_dec2,
                                        b_dec2, w_dec3, b_dec3, (float*)d_out,
                                        N);
}